// round 17
// baseline (speedup 1.0000x reference)
#include <cuda_runtime.h>
#include <math.h>
#include <float.h>

// Problem constants (fixed by setup_inputs)
#define BB 4
#define CC 256
#define MM 1024
#define NN 16384
#define HH 224
#define WW 224
#define HWH (HH*WW)
#define KPOOL 4
#define OH (HH/KPOOL)   // 56
#define OW (WW/KPOOL)   // 56
#define PP (OH*OW)      // 3136 pool cells
#define TPB 128         // threads per block in fused kernel

// Scratch (zero-initialized at module load; every launch restores zeros)
__device__ float g_xt[(size_t)BB * MM * CC];    // fp32 transposed feats [b][m][c] (4MB)
__device__ float g_pool[(size_t)BB * PP * CC];  // pooled accumulator (12.8MB)
__device__ float g_cnt[(size_t)BB * HWH];       // per-pixel point count (800KB)

// ---------------------------------------------------------------------------
// Bit-exact helpers (DO NOT TOUCH — these fix the discrete selection/binning)
// ---------------------------------------------------------------------------
__device__ __forceinline__ float norm3_ref(float x, float y, float z) {
    return __fadd_rn(__fadd_rn(__fmul_rn(x, x), __fmul_rn(y, y)), __fmul_rn(z, z));
}
// Projection row: NO-FMA ascending chain (matches XLA elementwise lowering)
__device__ __forceinline__ float proj_row(float k0, float k1, float k2,
                                          float x, float y, float z) {
    return __fadd_rn(__fadd_rn(__fmul_rn(k0, x), __fmul_rn(k1, y)), __fmul_rn(k2, z));
}
__device__ __forceinline__ int pixel_of(const float* __restrict__ Km,
                                        float px, float py, float pz) {
    float uz0 = proj_row(Km[0], Km[1], Km[2], px, py, pz);
    float uz1 = proj_row(Km[3], Km[4], Km[5], px, py, pz);
    float uz2 = proj_row(Km[6], Km[7], Km[8], px, py, pz);
    float zden = fmaxf(uz2, 1e-8f);
    float uf = floorf(__fdiv_rn(uz0, zden));
    float vf = floorf(__fdiv_rn(uz1, zden));
    int u = (int)fminf(fmaxf(uf, 0.0f), (float)(WW - 1));
    int v = (int)fminf(fmaxf(vf, 0.0f), (float)(HH - 1));
    return v * WW + u;
}
__device__ __forceinline__ float dist_exact(float px, float py, float pz, float pn,
                                            float4 c) {
    float dot = fmaf(pz, c.z, fmaf(py, c.y, __fmul_rn(px, c.x)));
    return __fsub_rn(__fadd_rn(pn, c.w), __fmul_rn(2.0f, dot));
}
__device__ __forceinline__ void red_add_v4(float* addr, float4 v) {
    asm volatile("red.global.add.v4.f32 [%0], {%1, %2, %3, %4};"
                 :: "l"(addr), "f"(v.x), "f"(v.y), "f"(v.z), "f"(v.w)
                 : "memory");
}

// ---------------------------------------------------------------------------
// Kernel 1: vectorized transpose xyz_feats [B][C][M] -> g_xt [B][M][C].
// Tile 64 m x 64 c. grid (MM/64=16, CC/64=4, BB); block 256.
// Per thread: 4x LDG.128 (MLP 4), smem transpose, 4x STG.128.
// ---------------------------------------------------------------------------
__global__ void __launch_bounds__(256) k_transpose(const float* __restrict__ X) {
    __shared__ float tile[64][65];   // [c][m]
    int b  = blockIdx.z;
    int m0 = blockIdx.x * 64;
    int c0 = blockIdx.y * 64;
    int tid = threadIdx.x;

    float4 v[4];
    #pragma unroll
    for (int r = 0; r < 4; r++) {
        int w = tid + 256 * r;           // 0..1023 over (64 c) x (16 m4)
        int c = w >> 4, m4 = w & 15;
        v[r] = *reinterpret_cast<const float4*>(
            &X[((size_t)b * CC + c0 + c) * MM + m0 + m4 * 4]);
    }
    #pragma unroll
    for (int r = 0; r < 4; r++) {
        int w = tid + 256 * r;
        int c = w >> 4, m4 = w & 15;
        tile[c][m4 * 4 + 0] = v[r].x;
        tile[c][m4 * 4 + 1] = v[r].y;
        tile[c][m4 * 4 + 2] = v[r].z;
        tile[c][m4 * 4 + 3] = v[r].w;
    }
    __syncthreads();
    #pragma unroll
    for (int r = 0; r < 4; r++) {
        int w = tid + 256 * r;           // over (64 m) x (16 c4)
        int m = w >> 4, c4 = w & 15;
        float4 f;
        f.x = tile[c4 * 4 + 0][m];
        f.y = tile[c4 * 4 + 1][m];
        f.z = tile[c4 * 4 + 2][m];
        f.w = tile[c4 * 4 + 3][m];
        *reinterpret_cast<float4*>(
            &g_xt[((size_t)b * MM + m0 + m) * CC + c0 + c4 * 4]) = f;
    }
}

// ---------------------------------------------------------------------------
// Kernel 2: per-pixel point counts (tiny)
// ---------------------------------------------------------------------------
__global__ void __launch_bounds__(256) k_count(
    const float* __restrict__ pts, const float* __restrict__ Km)
{
    int b = blockIdx.y;
    int n = blockIdx.x * 256 + threadIdx.x;
    const float* p = &pts[((size_t)b * NN + n) * 3];
    int pix = pixel_of(Km, p[0], p[1], p[2]);
    atomicAdd(&g_cnt[(size_t)b * HWH + pix], 1.0f);
}

// ---------------------------------------------------------------------------
// Kernel 3: fused dense 3-NN + warp-cooperative gather/scatter (R16, unchanged)
// ---------------------------------------------------------------------------
__global__ void __launch_bounds__(TPB) k_knn_scatter(
    const float* __restrict__ pts,   // [B][N][3]
    const float* __restrict__ ctr,   // [B][M][3]
    const float* __restrict__ Km)    // [3][3]
{
    __shared__ float4 sc[MM];        // centers (x,y,z,|c|^2)  16KB
    __shared__ int4   stg_i[TPB];    // (i0,i1,i2,dstCellBase) 2KB
    __shared__ float4 stg_w[TPB];    // (w0s,w1s,w2s,-)        2KB

    int b   = blockIdx.y;
    int tid = threadIdx.x;
    int lane = tid & 31;

    for (int i = tid; i < MM; i += TPB) {
        float x = ctr[((size_t)b * MM + i) * 3 + 0];
        float y = ctr[((size_t)b * MM + i) * 3 + 1];
        float z = ctr[((size_t)b * MM + i) * 3 + 2];
        sc[i] = make_float4(x, y, z, norm3_ref(x, y, z));
    }

    int n = blockIdx.x * TPB + tid;   // grid.x = NN/TPB -> exact
    const float* p = &pts[((size_t)b * NN + n) * 3];
    float px = __ldg(&p[0]), py = __ldg(&p[1]), pz = __ldg(&p[2]);
    float pn = norm3_ref(px, py, pz);

    // pixel + count prefetch: issued BEFORE the 1024-iter loop (latency hidden)
    int pix = pixel_of(Km, px, py, pz);
    float cnt = __ldg(&g_cnt[(size_t)b * HWH + pix]);

    __syncthreads();

    // ---- dense top-3: strict-<, ascending m (ties -> earliest index) ----
    float d0 = FLT_MAX, d1 = FLT_MAX, d2 = FLT_MAX;
    int   i0 = 0, i1 = 0, i2 = 0;
    #pragma unroll 8
    for (int m = 0; m < MM; m++) {
        float d = dist_exact(px, py, pz, pn, sc[m]);   // broadcast LDS.128
        if (d < d2) {
            if (d < d1) {
                d2 = d1; i2 = i1;
                if (d < d0) { d1 = d0; i1 = i0; d0 = d; i0 = m; }
                else        { d1 = d;  i1 = m; }
            } else { d2 = d; i2 = m; }
        }
    }

    // ---- weights (exact IEEE divisions) ----
    float w0 = __fdiv_rn(1.0f, __fadd_rn(d0, 1e-8f));
    float w1 = __fdiv_rn(1.0f, __fadd_rn(d1, 1e-8f));
    float w2 = __fdiv_rn(1.0f, __fadd_rn(d2, 1e-8f));
    float ws = __fadd_rn(__fadd_rn(w0, w1), w2);
    w0 = __fdiv_rn(w0, ws); w1 = __fdiv_rn(w1, ws); w2 = __fdiv_rn(w2, ws);

    // ---- per-point scale = (1/count) * (1/16); dst cell ----
    float scale = __fdiv_rn(1.0f, cnt) * 0.0625f;
    int v = pix / WW, u = pix % WW;
    int cell = (v >> 2) * OW + (u >> 2);
    int dstBase = (b * PP + cell) * CC;

    stg_i[tid] = make_int4(i0, i1, i2, dstBase);
    stg_w[tid] = make_float4(w0 * scale, w1 * scale, w2 * scale, 0.0f);
    __syncwarp();

    // ---- warp-cooperative gather + vector scatter ----
    const float4* xt4 = reinterpret_cast<const float4*>(g_xt);
    int wbase = tid & ~31;
    #pragma unroll 4
    for (int k = 0; k < 32; k++) {
        int4   si = stg_i[wbase + k];   // broadcast
        float4 sw = stg_w[wbase + k];
        const float4* r0 = xt4 + ((size_t)b * MM + si.x) * (CC / 4);
        const float4* r1 = xt4 + ((size_t)b * MM + si.y) * (CC / 4);
        const float4* r2 = xt4 + ((size_t)b * MM + si.z) * (CC / 4);
        float* dp = &g_pool[si.w];
        #pragma unroll
        for (int j = 0; j < 2; j++) {
            int c4 = j * 32 + lane;
            float4 a  = __ldg(&r0[c4]);
            float4 bq = __ldg(&r1[c4]);
            float4 cq = __ldg(&r2[c4]);
            float4 f;
            f.x = fmaf(sw.x, a.x, fmaf(sw.y, bq.x, sw.z * cq.x));
            f.y = fmaf(sw.x, a.y, fmaf(sw.y, bq.y, sw.z * cq.y));
            f.z = fmaf(sw.x, a.z, fmaf(sw.y, bq.z, sw.z * cq.z));
            f.w = fmaf(sw.x, a.w, fmaf(sw.y, bq.w, sw.z * cq.w));
            red_add_v4(dp + c4 * 4, f);
        }
    }
}

// ---------------------------------------------------------------------------
// Kernel 4: vectorized transpose g_pool [b][p][c] -> out [b][c][p] + clear.
// Tile: 64 cells x 128 channels (two 64x65 smem tiles), 8 independent
// LDG.128 per thread (MLP 8). grid (49, 2, 4); block 256.
// ---------------------------------------------------------------------------
__global__ void __launch_bounds__(256) k_pool_out(float* __restrict__ out) {
    __shared__ float tileA[64][65];  // channels c0 .. c0+63
    __shared__ float tileB[64][65];  // channels c0+64 .. c0+127
    int b  = blockIdx.z;
    int c0 = blockIdx.y * 128;
    int p0 = blockIdx.x * 64;
    int tid = threadIdx.x;

    float4 vA[4], vB[4];
    #pragma unroll
    for (int r = 0; r < 4; r++) {
        int w = tid + 256 * r;
        int cell = w >> 4, c4 = w & 15;
        size_t idx = ((size_t)b * PP + p0 + cell) * CC + c0 + c4 * 4;
        vA[r] = *reinterpret_cast<const float4*>(&g_pool[idx]);
        vB[r] = *reinterpret_cast<const float4*>(&g_pool[idx + 64]);
    }
    const float4 z4 = make_float4(0.f, 0.f, 0.f, 0.f);
    #pragma unroll
    for (int r = 0; r < 4; r++) {
        int w = tid + 256 * r;
        int cell = w >> 4, c4 = w & 15;
        size_t idx = ((size_t)b * PP + p0 + cell) * CC + c0 + c4 * 4;
        *reinterpret_cast<float4*>(&g_pool[idx]) = z4;        // restore invariant
        *reinterpret_cast<float4*>(&g_pool[idx + 64]) = z4;
        tileA[cell][c4 * 4 + 0] = vA[r].x;
        tileA[cell][c4 * 4 + 1] = vA[r].y;
        tileA[cell][c4 * 4 + 2] = vA[r].z;
        tileA[cell][c4 * 4 + 3] = vA[r].w;
        tileB[cell][c4 * 4 + 0] = vB[r].x;
        tileB[cell][c4 * 4 + 1] = vB[r].y;
        tileB[cell][c4 * 4 + 2] = vB[r].z;
        tileB[cell][c4 * 4 + 3] = vB[r].w;
    }
    if (blockIdx.y == 0) {
        #pragma unroll
        for (int k = 0; k < 4; k++) {
            int i = blockIdx.x * 256 + tid + k * (49 * 256);
            g_cnt[(size_t)b * HWH + i] = 0.0f;   // 49*256*4 = 50176 = HWH
        }
    }
    __syncthreads();

    #pragma unroll
    for (int r = 0; r < 4; r++) {
        int w = tid + 256 * r;
        int c = w >> 4, p4 = w & 15;
        float4 fA, fB;
        fA.x = tileA[p4 * 4 + 0][c];
        fA.y = tileA[p4 * 4 + 1][c];
        fA.z = tileA[p4 * 4 + 2][c];
        fA.w = tileA[p4 * 4 + 3][c];
        fB.x = tileB[p4 * 4 + 0][c];
        fB.y = tileB[p4 * 4 + 1][c];
        fB.z = tileB[p4 * 4 + 2][c];
        fB.w = tileB[p4 * 4 + 3][c];
        *reinterpret_cast<float4*>(
            &out[((size_t)b * CC + c0 + c) * PP + p0 + p4 * 4]) = fA;
        *reinterpret_cast<float4*>(
            &out[((size_t)b * CC + c0 + 64 + c) * PP + p0 + p4 * 4]) = fB;
    }
}

// ---------------------------------------------------------------------------
extern "C" void kernel_launch(void* const* d_in, const int* in_sizes, int n_in,
                              void* d_out, int out_size) {
    const float* feats = (const float*)d_in[0];  // [B][C][M]
    const float* pts   = (const float*)d_in[1];  // [B][N][3]
    const float* ctr   = (const float*)d_in[2];  // [B][M][3]
    const float* Km    = (const float*)d_in[3];  // [3][3]
    float* out = (float*)d_out;

    k_transpose<<<dim3(MM / 64, CC / 64, BB), 256>>>(feats);
    k_count<<<dim3(NN / 256, BB), 256>>>(pts, Km);
    k_knn_scatter<<<dim3(NN / TPB, BB), TPB>>>(pts, ctr, Km);
    k_pool_out<<<dim3(PP / 64, CC / 128, BB), 256>>>(out);
}